// round 15
// baseline (speedup 1.0000x reference)
#include <cuda_runtime.h>
#include <cuda_bf16.h>
#include <cuda_fp16.h>
#include <cstdint>

#define BATCH 8
#define NN 2048
#define EE 2048

#define BM 256
#define BN 128
#define STAGES 4
#define STAGE_BYTES 49152       // A: 256x128B (32KB) + B: 128x128B (16KB)
#define STAT_BYTES 2048         // 512 x float column-max scratch
#define CAP 2048                // per-row sparse capacity (cannot overflow)
#define ECH 64                  // spmm entry-chunk per pass
#define MG  16                  // spmm m-group

// ---------------- scratch globals (no cudaMalloc allowed) ----------------
__device__ __align__(256) __nv_bfloat16 g_xh[(size_t)BATCH * NN * EE];
__device__ __align__(256) __nv_bfloat16 g_xl[(size_t)BATCH * NN * EE];
__device__ __align__(256) __half        g_xt[(size_t)BATCH * NN * EE];   // X^T per batch [e][n], fp16
__device__ __align__(256) __nv_bfloat16 g_wh[(size_t)EE * EE];
__device__ __align__(256) __nv_bfloat16 g_wl[(size_t)EE * EE];
__device__ __align__(256) float         g_q [(size_t)BATCH * NN * EE];   // exact fp32 Q
__device__ __align__(256) __nv_bfloat16 g_qh[(size_t)BATCH * NN * EE];
__device__ __align__(256) __nv_bfloat16 g_s [(size_t)BATCH * NN * NN];   // approx scores (bf16)
__device__ __align__(256) float         g_pm[BATCH * 8 * NN];
__device__ __align__(256) float         g_cmax[BATCH * NN];    // approx cmax, later exact
__device__ __align__(256) float         g_csum[BATCH * NN];    // exact 1/sum
__device__ __align__(256) unsigned      g_ck[BATCH * NN];      // encoded col max key
__device__ __align__(256) float         g_cs[BATCH * NN];      // col sum accumulator
__device__ __align__(256) int           g_cnt[BATCH * NN];
__device__ __align__(256) uint2         g_ent[(size_t)BATCH * NN * CAP]; // (e, score bits)

// ---------------- helpers ----------------
__device__ __forceinline__ uint32_t smem_u32(const void* p) {
    uint32_t a;
    asm("{ .reg .u64 t; cvta.to.shared.u64 t, %1; cvt.u32.u64 %0, t; }" : "=r"(a) : "l"(p));
    return a;
}
__device__ __forceinline__ void cp16(uint32_t s, const void* g) {
    asm volatile("cp.async.cg.shared.global [%0], [%1], 16;" :: "r"(s), "l"(g) : "memory");
}
__device__ __forceinline__ void cp_commit() {
    asm volatile("cp.async.commit_group;" ::: "memory");
}
template <int N> __device__ __forceinline__ void cp_wait() {
    asm volatile("cp.async.wait_group %0;" :: "n"(N) : "memory");
}
__device__ __forceinline__ void ldm4(uint32_t* r, uint32_t a) {
    asm volatile("ldmatrix.sync.aligned.m8n8.x4.shared.b16 {%0,%1,%2,%3}, [%4];"
                 : "=r"(r[0]), "=r"(r[1]), "=r"(r[2]), "=r"(r[3]) : "r"(a));
}
__device__ __forceinline__ void mma16816(float* c, const uint32_t* a, uint32_t b0, uint32_t b1) {
    asm volatile(
        "mma.sync.aligned.m16n8k16.row.col.f32.bf16.bf16.f32 "
        "{%0,%1,%2,%3}, {%4,%5,%6,%7}, {%8,%9}, {%0,%1,%2,%3};"
        : "+f"(c[0]), "+f"(c[1]), "+f"(c[2]), "+f"(c[3])
        : "r"(a[0]), "r"(a[1]), "r"(a[2]), "r"(a[3]), "r"(b0), "r"(b1));
}
// monotonic float<->uint for atomicMax over signed floats
__device__ __forceinline__ unsigned fenc(float f) {
    unsigned u = __float_as_uint(f);
    return (u & 0x80000000u) ? ~u : (u | 0x80000000u);
}
__device__ __forceinline__ float fdec(unsigned u) {
    u = (u & 0x80000000u) ? (u & 0x7FFFFFFFu) : ~u;
    return __uint_as_float(u);
}

// ---------------- persistent tensor-core GEMM: C tiles 256x128 = A @ B^T ----------------
// NBK=96: 3-phase bf16 split (Ah,Bh)/(Al,Bh)/(Ah,Bl).  NBK=32: 1-phase (Ah,Bh).
// MODE 0: fp32 out.  MODE 1: fp32 out AND bf16(out) to outH.  MODE 2: bf16 out only.
// STATS: fused per-tile column MAX (for candidate thresholding).
template <int MODE, bool STATS, int NBK>
__global__ __launch_bounds__(256, 1)
void gemm_mma(const void* Ahv, const void* Alv, const void* Bhv, const void* Blv,
              long long aBatch, long long bBatch, long long cBatch,
              float* outF, __nv_bfloat16* outH,
              int gx, int gy, int nTiles, float* pm)
{
    extern __shared__ __align__(128) char smem[];
    const uint32_t stg0 = smem_u32(smem);
    const int tid  = threadIdx.x;
    const int lane = tid & 31;
    const int warp = tid >> 5;

    const int lr = tid >> 3;
    const int lc = tid & 7;
    const uint32_t so = (uint32_t)(lr * 128 + ((lc ^ (lr & 7)) << 4));

    const int wm  = warp & 3;
    const int wn  = warp >> 2;
    const int m0w = wm * 64;
    const int n0w = wn * 64;
    const uint32_t aRow  = (uint32_t)(m0w + (lane & 15));
    const uint32_t aBase = aRow * 128;
    const uint32_t aXor  = aRow & 7;
    const uint32_t ac0   = (uint32_t)(lane >> 4);
    const uint32_t bRow  = (uint32_t)(n0w + ((lane >> 4) << 3) + (lane & 7));
    const uint32_t bBase = 32768u + bRow * 128;
    const uint32_t bXor  = (uint32_t)(lane & 7);
    const uint32_t bc0   = (uint32_t)((lane >> 3) & 1);

    float acc[4][8][4] = {};
    uint32_t af[2][4][4], bf[2][4][4];

    const char *gAh, *gAl, *gBh, *gBl;
    auto setLoad = [&](int t) {
        const int bx = t % gx;
        const int r2 = t / gx;
        const int by = r2 % gy;
        const int bz = r2 / gy;
        const size_t aoff = ((size_t)bz * (size_t)aBatch + (size_t)(by * BM + lr) * EE) * 2 + lc * 16;
        const size_t boff = ((size_t)bz * (size_t)bBatch + (size_t)(bx * BN + lr) * EE) * 2 + lc * 16;
        gAh = (const char*)Ahv + aoff;
        gAl = (const char*)Alv + aoff;
        gBh = (const char*)Bhv + boff;
        gBl = (const char*)Blv + boff;
    };

    auto load_chunk = [&](int s, int kbn, int part) {
        const int p = kbn >> 5;
        const char* a = (p == 1) ? gAl : gAh;
        const char* b = (p == 2) ? gBl : gBh;
        const uint32_t koff = (uint32_t)(kbn & 31) * 128;
        const uint32_t dstA = stg0 + (uint32_t)s * STAGE_BYTES + so;
        const uint32_t dstB = dstA + 32768u;
        cp16(dstA + (uint32_t)(part * 2)     * 4096u, a + koff + (size_t)(part * 2)     * 131072);
        cp16(dstA + (uint32_t)(part * 2 + 1) * 4096u, a + koff + (size_t)(part * 2 + 1) * 131072);
        cp16(dstB + (uint32_t)part           * 4096u, b + koff + (size_t)part           * 131072);
        if (part == 3) cp_commit();
    };
    auto ldm_ks = [&](uint32_t sb_, uint32_t ke, int bsel) {
#pragma unroll
        for (int mt = 0; mt < 4; mt++)
            ldm4(af[bsel][mt], sb_ + aBase + mt * 2048u + (((ke * 2 + ac0) ^ aXor) << 4));
#pragma unroll
        for (int np = 0; np < 4; np++)
            ldm4(bf[bsel][np], sb_ + bBase + np * 2048u + (((ke * 2 + bc0) ^ bXor) << 4));
    };

    int t = blockIdx.x;
    if (t >= nTiles) return;
    setLoad(t);
#pragma unroll
    for (int st = 0; st < 3; st++)
        for (int part = 0; part < 4; part++) load_chunk(st, st, part);
    cp_wait<1>();
    __syncthreads();
    ldm_ks(stg0, 0, 0);

    for (;;) {
        const int bx = t % gx;
        const int r2 = t / gx;
        const int row0 = (r2 % gy) * BM;
        const int col0 = bx * BN;
        const int z    = r2 / gy;
        const bool hasNext = (t + (int)gridDim.x) < nTiles;

        for (int kb = 0; kb < NBK; kb++) {
            if (kb == NBK - 3 && hasNext) setLoad(t + (int)gridDim.x);
            const bool doLoad = (kb < NBK - 3) || hasNext;
            const int  kbn    = (kb + 3 < NBK) ? (kb + 3) : (kb + 3 - NBK);
            const uint32_t sb = stg0 + (uint32_t)(kb & 3) * STAGE_BYTES;
#pragma unroll
            for (int ks = 0; ks < 4; ks++) {
                if (doLoad) load_chunk((kb + 3) & 3, kbn, ks);
                const int cur = ks & 1;
                if (ks < 3)
                    ldm_ks(sb, (uint32_t)ks + 1, cur ^ 1);
                else if (kb + 1 < NBK)
                    ldm_ks(stg0 + (uint32_t)((kb + 1) & 3) * STAGE_BYTES, 0, cur ^ 1);
#pragma unroll
                for (int mt = 0; mt < 4; mt++)
#pragma unroll
                    for (int np = 0; np < 4; np++) {
                        mma16816(acc[mt][np * 2],     af[cur][mt], bf[cur][np][0], bf[cur][np][1]);
                        mma16816(acc[mt][np * 2 + 1], af[cur][mt], bf[cur][np][2], bf[cur][np][3]);
                    }
            }
            if (kb + 1 < NBK) {
                if (doLoad) cp_wait<1>(); else cp_wait<0>();
                __syncthreads();
            }
        }
        if (hasNext) cp_wait<1>(); else cp_wait<0>();
        __syncthreads();
        if (hasNext) ldm_ks(stg0, 0, 0);

        // -------- epilogue --------
        const int g  = lane >> 2;
        const int tg = lane & 3;
#pragma unroll
        for (int mt = 0; mt < 4; mt++) {
            const int rg = row0 + m0w + mt * 16 + g;
#pragma unroll
            for (int nt = 0; nt < 8; nt++) {
                const int cg = col0 + n0w + nt * 8 + 2 * tg;
                if (MODE == 0 || MODE == 1) {
                    float* base = outF + (size_t)z * (size_t)cBatch;
                    *(float2*)(base + (size_t)rg * 2048 + cg)       = make_float2(acc[mt][nt][0], acc[mt][nt][1]);
                    *(float2*)(base + (size_t)(rg + 8) * 2048 + cg) = make_float2(acc[mt][nt][2], acc[mt][nt][3]);
                }
                if (MODE == 1 || MODE == 2) {
                    __nv_bfloat16* hb = outH + (size_t)z * (size_t)cBatch;
                    *(__nv_bfloat162*)(hb + (size_t)rg * 2048 + cg) =
                        __nv_bfloat162(__float2bfloat16(acc[mt][nt][0]), __float2bfloat16(acc[mt][nt][1]));
                    *(__nv_bfloat162*)(hb + (size_t)(rg + 8) * 2048 + cg) =
                        __nv_bfloat162(__float2bfloat16(acc[mt][nt][2]), __float2bfloat16(acc[mt][nt][3]));
                }
            }
        }
        if (STATS) {
            float* sst = (float*)(smem + STAGES * STAGE_BYTES);
#pragma unroll
            for (int nt = 0; nt < 8; nt++) {
#pragma unroll
                for (int p = 0; p < 2; p++) {
                    float m = acc[0][nt][p];
#pragma unroll
                    for (int mt = 0; mt < 4; mt++) {
                        m = fmaxf(m, acc[mt][nt][p]);
                        m = fmaxf(m, acc[mt][nt][2 + p]);
                    }
#pragma unroll
                    for (int off = 4; off < 32; off <<= 1)
                        m = fmaxf(m, __shfl_xor_sync(0xffffffffu, m, off));
                    if (lane < 4) {
                        const int colLocal = n0w + nt * 8 + lane * 2 + p;
                        sst[colLocal * 4 + wm] = m;
                    }
                }
            }
            __syncthreads();
            if (tid < 128) {
                float M = fmaxf(fmaxf(sst[tid * 4 + 0], sst[tid * 4 + 1]),
                                fmaxf(sst[tid * 4 + 2], sst[tid * 4 + 3]));
                const size_t o = ((size_t)z * (size_t)gy + (size_t)(row0 / BM)) * NN
                               + (size_t)(col0 + tid);
                pm[o] = M;
            }
            __syncthreads();
        }
        if (!hasNext) break;
#pragma unroll
        for (int mt = 0; mt < 4; mt++)
#pragma unroll
            for (int nt = 0; nt < 8; nt++)
#pragma unroll
                for (int q = 0; q < 4; q++) acc[mt][nt][q] = 0.0f;
        t += (int)gridDim.x;
    }
}

// ---------------- fused prep: X -> (bf16 hi/lo + fp16 transpose), W -> bf16 hi/lo ----------------
__global__ __launch_bounds__(256)
void prep(const float* __restrict__ X, const float* __restrict__ W,
          __nv_bfloat16* __restrict__ xh, __nv_bfloat16* __restrict__ xl,
          __half* __restrict__ xt,
          __nv_bfloat16* __restrict__ wh, __nv_bfloat16* __restrict__ wl)
{
    const int c  = threadIdx.x & 31;
    const int r0 = threadIdx.x >> 5;
    const int e0 = blockIdx.x * 32;
    const int n0 = blockIdx.y * 32;
    if (blockIdx.z == 8) {
#pragma unroll
        for (int k = 0; k < 4; k++) {
            const int r = r0 + k * 8;
            const size_t i = (size_t)(n0 + r) * EE + e0 + c;
            const float v = W[i];
            const __nv_bfloat16 h = __float2bfloat16(v);
            wh[i] = h;
            wl[i] = __float2bfloat16(v - __bfloat162float(h));
        }
        return;
    }
    __shared__ float tile[32][33];
    const int b = blockIdx.z;
    const float* Xb  = X  + (size_t)b * NN * EE;
    __half*      xtb = xt + (size_t)b * NN * EE;
#pragma unroll
    for (int k = 0; k < 4; k++) {
        const int r = r0 + k * 8;
        const size_t i = (size_t)(n0 + r) * EE + e0 + c;
        const float v = Xb[i];
        tile[r][c] = v;
        const __nv_bfloat16 h = __float2bfloat16(v);
        xh[(size_t)b * NN * EE + i] = h;
        xl[(size_t)b * NN * EE + i] = __float2bfloat16(v - __bfloat162float(h));
    }
    __syncthreads();
#pragma unroll
    for (int k = 0; k < 4; k++) {
        const int r = r0 + k * 8;
        xtb[(size_t)(e0 + r) * NN + n0 + c] = __float2half(tile[c][r]);
    }
}

// ---------------- combine approx per-tile maxes -> approx cmax; init exact accumulators ----
__global__ void col_finish(const float* __restrict__ pm, float* __restrict__ cmax,
                           unsigned* __restrict__ ck, float* __restrict__ cs)
{
    const int i = blockIdx.x * blockDim.x + threadIdx.x;
    const int b = i >> 11, col = i & 2047;
    const float* pmb = pm + (size_t)b * 8 * NN + col;
    float M = pmb[0];
#pragma unroll
    for (int t2 = 1; t2 < 8; t2++) M = fmaxf(M, pmb[(size_t)t2 * NN]);
    cmax[i] = M;
    ck[i] = 0u;      // encoded -inf
    cs[i] = 0.0f;
}

// ---------------- candidate extraction on APPROX bf16 scores (threshold -21.5) ----------
// Approx error (1-phase mma ~0.04 + bf16 storage ~0.09, 5-sigma < 0.7) << margin 1.5:
// dropped true weight < ~e^-20: unconditionally safe.
__global__ __launch_bounds__(256)
void extract(const __nv_bfloat16* __restrict__ S, const float* __restrict__ cmax,
             int* __restrict__ cnt, uint2* __restrict__ ent)
{
    const int gw   = (int)((blockIdx.x * blockDim.x + threadIdx.x) >> 5);
    const int lane = threadIdx.x & 31;
    const int b = gw >> 11;
    const __nv_bfloat16* Srow = S + (size_t)gw * NN;
    const float* cmb = cmax + b * NN;
    uint2* rowEnt = ent + (size_t)gw * CAP;

    int count = 0;
    for (int it = 0; it < 8; it++) {
        const int j0 = it * 256 + lane * 8;
        const uint4 raw = *(const uint4*)(Srow + j0);          // 8 bf16
        const float4 mx0 = *(const float4*)(cmb + j0);
        const float4 mx1 = *(const float4*)(cmb + j0 + 4);
        const unsigned rw[4] = {raw.x, raw.y, raw.z, raw.w};
        float vs[8];
#pragma unroll
        for (int h = 0; h < 4; h++) {
            vs[h * 2]     = __bfloat162float(__ushort_as_bfloat16((unsigned short)(rw[h] & 0xFFFFu)));
            vs[h * 2 + 1] = __bfloat162float(__ushort_as_bfloat16((unsigned short)(rw[h] >> 16)));
        }
        const float ms[8] = {mx0.x, mx0.y, mx0.z, mx0.w, mx1.x, mx1.y, mx1.z, mx1.w};
#pragma unroll
        for (int c = 0; c < 8; c++) {
            const bool keep = (vs[c] - ms[c]) > -21.5f;
            const unsigned bal = __ballot_sync(0xffffffffu, keep);
            if (keep) {
                const int pos = count + __popc(bal & ((1u << lane) - 1u));
                rowEnt[pos] = make_uint2((unsigned)(j0 + c), 0u);
            }
            count += __popc(bal);
        }
    }
    if (lane == 0) cnt[gw] = count;
}

// ---------------- exact score recompute for candidates; exact column max ----------------
// Block per attn-row (b,m): Q row cached in smem; warp per candidate dot (fp32).
__global__ __launch_bounds__(256)
void recompute(const float* __restrict__ Q, const float* __restrict__ X,
               const int* __restrict__ cnt, uint2* __restrict__ ent,
               unsigned* __restrict__ ck)
{
    __shared__ float qs[EE];
    const int row  = blockIdx.x;            // b*NN + m
    const int tid  = threadIdx.x;
    const int lane = tid & 31;
    const int w    = tid >> 5;              // 0..7
    const int c    = cnt[row];
    const float4* qrow = (const float4*)(Q + (size_t)row * EE);
#pragma unroll
    for (int i = 0; i < 2; i++) ((float4*)qs)[tid + i * 256] = qrow[tid + i * 256];
    __syncthreads();

    const int b = row >> 11;
    const float* Xb = X + (size_t)b * NN * EE;
    uint2* re = ent + (size_t)row * CAP;
    for (int idx = w; idx < c; idx += 8) {
        const int e = (int)re[idx].x;
        const float4* xr = (const float4*)(Xb + (size_t)e * EE);
        float sum = 0.0f;
#pragma unroll
        for (int i = 0; i < 16; i++) {
            const float4 a  = ((const float4*)qs)[lane + i * 32];
            const float4 x4 = xr[lane + i * 32];
            sum += a.x * x4.x + a.y * x4.y + a.z * x4.z + a.w * x4.w;
        }
#pragma unroll
        for (int off = 16; off; off >>= 1) sum += __shfl_xor_sync(0xffffffffu, sum, off);
        if (lane == 0) {
            re[idx].y = __float_as_uint(sum);
            atomicMax(&ck[b * NN + e], fenc(sum));
        }
    }
}

// ---------------- column denominator over candidates (exact scores) ----------------
__global__ __launch_bounds__(256)
void colsum_pass(const int* __restrict__ cnt, const uint2* __restrict__ ent,
                 const unsigned* __restrict__ ck, float* __restrict__ cs)
{
    const int gw   = blockIdx.x * 8 + (threadIdx.x >> 5);
    const int lane = threadIdx.x & 31;
    const int b = gw >> 11;
    const int c = cnt[gw];
    const uint2* re = ent + (size_t)gw * CAP;
    for (int idx = lane; idx < c; idx += 32) {
        const uint2 p = re[idx];
        const int be = b * NN + (int)p.x;
        atomicAdd(&cs[be], __expf(__uint_as_float(p.y) - fdec(ck[be])));
    }
}

__global__ void finalize_cols(const unsigned* __restrict__ ck, const float* __restrict__ cs,
                              float* __restrict__ cmax, float* __restrict__ crsum)
{
    const int i = blockIdx.x * blockDim.x + threadIdx.x;
    cmax[i]  = fdec(ck[i]);
    crsum[i] = 1.0f / cs[i];
}

// ---------------- sparse output: out[b,n,m] = sum_e w[m,e] * xt[b,e,n] ----------------
__global__ __launch_bounds__(256)
void spmm_out(const __half* __restrict__ xt, const int* __restrict__ cnt,
              const uint2* __restrict__ ent,
              const float* __restrict__ cmax, const float* __restrict__ crsum,
              float* __restrict__ out)
{
    extern __shared__ __align__(16) char dsm[];
    uint2 (*sent)[ECH] = (uint2 (*)[ECH])dsm;            // [MG][ECH] = 8KB
    int*   scnt        = (int*)(dsm + MG * ECH * 8);     // [MG]
    float (*buf)[17]   = (float (*)[17])dsm;             // write staging (reuses dsm)

    const int mg = blockIdx.x;
    const int b  = blockIdx.y;
    const int m0 = mg * MG;
    const int tid = threadIdx.x;
    const __half* xtb = xt + (size_t)b * NN * EE;
    float* outb = out + (size_t)b * NN * NN;

    if (tid < MG) scnt[tid] = cnt[b * NN + m0 + tid];
    __syncthreads();
    int maxc = 0;
#pragma unroll
    for (int j = 0; j < MG; j++) maxc = max(maxc, scnt[j]);

    float acc[8][MG];
#pragma unroll
    for (int k = 0; k < 8; k++)
#pragma unroll
        for (int j = 0; j < MG; j++) acc[k][j] = 0.0f;

    const int passes = (maxc + ECH - 1) / ECH;
    for (int pass = 0; pass < passes; pass++) {
        const int srow  = tid >> 4;
        const int base  = pass * ECH;
        const int avail = min(scnt[srow] - base, ECH);
#pragma unroll
        for (int s2 = 0; s2 < ECH / 16; s2++) {
            const int slot = (tid & 15) + s2 * 16;
            if (slot < avail) {
                uint2 p = ent[(size_t)(b * NN + m0 + srow) * CAP + base + slot];
                const int be = b * NN + (int)p.x;
                const float w = __expf(__uint_as_float(p.y) - __ldg(cmax + be)) * __ldg(crsum + be);
                sent[srow][slot] = make_uint2(p.x, __float_as_uint(w));
            }
        }
        __syncthreads();
#pragma unroll
        for (int j = 0; j < MG; j++) {
            const int cj = min(scnt[j] - base, ECH);
            for (int idx = 0; idx < cj; idx++) {
                const uint2 p = sent[j][idx];
                const float w = __uint_as_float(p.y);
                const __half* xr = xtb + (size_t)p.x * NN + tid;
#pragma unroll
                for (int k = 0; k < 8; k++)
                    acc[k][j] = fmaf(w, __half2float(__ldg(xr + k * 256)), acc[k][j]);
            }
        }
        __syncthreads();
    }

#pragma unroll
    for (int k = 0; k < 8; k++) {
        __syncthreads();
#pragma unroll
        for (int j = 0; j < MG; j++) buf[tid][j] = acc[k][j];
        __syncthreads();
#pragma unroll
        for (int s2 = 0; s2 < 4; s2++) {
            const int lin = s2 * 256 + tid;
            const int r   = lin >> 2;
            const int c4  = (lin & 3) * 4;
            const int n   = k * 256 + r;
            *(float4*)(outb + (size_t)n * NN + m0 + c4) =
                make_float4(buf[r][c4], buf[r][c4 + 1], buf[r][c4 + 2], buf[r][c4 + 3]);
        }
    }
}

// ---------------- launch ----------------
extern "C" void kernel_launch(void* const* d_in, const int* in_sizes, int n_in,
                              void* d_out, int out_size)
{
    const float* X = (const float*)d_in[0];
    const float* W = (const float*)d_in[1];
    // d_in[2] = bias: per-column constant on scores -> cancels in axis-1 softmax.
    // d_in[3] = gamma: scalar constant -> cancels likewise. Both unused.
    float* out = (float*)d_out;

    __nv_bfloat16 *xh, *xl, *wh, *wl, *qh, *sbf;
    __half *xt;
    float *q, *pm, *cmax, *csum, *cs;
    unsigned *ck;
    int *cnt; uint2 *ent;
    cudaGetSymbolAddress((void**)&xh, g_xh);  cudaGetSymbolAddress((void**)&xl, g_xl);
    cudaGetSymbolAddress((void**)&xt, g_xt);
    cudaGetSymbolAddress((void**)&wh, g_wh);  cudaGetSymbolAddress((void**)&wl, g_wl);
    cudaGetSymbolAddress((void**)&q,  g_q);   cudaGetSymbolAddress((void**)&qh, g_qh);
    cudaGetSymbolAddress((void**)&sbf, g_s);
    cudaGetSymbolAddress((void**)&pm, g_pm);
    cudaGetSymbolAddress((void**)&cmax, g_cmax);
    cudaGetSymbolAddress((void**)&csum, g_csum);
    cudaGetSymbolAddress((void**)&ck, g_ck);  cudaGetSymbolAddress((void**)&cs, g_cs);
    cudaGetSymbolAddress((void**)&cnt, g_cnt);
    cudaGetSymbolAddress((void**)&ent, g_ent);

    int dev = 0;  cudaGetDevice(&dev);
    int nsm = 148;
    cudaDeviceGetAttribute(&nsm, cudaDevAttrMultiProcessorCount, dev);

    const int smemG = STAGES * STAGE_BYTES + STAT_BYTES;
    cudaFuncSetAttribute((const void*)gemm_mma<1, false, 96>, cudaFuncAttributeMaxDynamicSharedMemorySize, smemG);
    cudaFuncSetAttribute((const void*)gemm_mma<2, true, 32>,  cudaFuncAttributeMaxDynamicSharedMemorySize, smemG);

    // prep: X -> xh/xl/xt, W -> wh/wl
    prep<<<dim3(64, 64, 9), 256>>>(X, W, xh, xl, xt, wh, wl);

    const long long sXE = (long long)NN * EE;
    const long long sNN = (long long)NN * NN;

    // GEMM1: Q = X W^T. 3-phase bf16 -> exact fp32 Q + bf16 qh.
    gemm_mma<1, false, 96><<<nsm, 256, smemG>>>(xh, xl, wh, wl, 0, 0, 0,
                                                q, qh, 16, 64, 1024, nullptr);

    // GEMM2: approx S[b] = Qh[b] Xh[b]^T. 1-phase bf16 -> bf16 S + fused col-max.
    gemm_mma<2, true, 32><<<nsm, 256, smemG>>>(qh, qh, xh, xh, sXE, sXE, sNN,
                                               nullptr, sbf, 16, 8, 1024, pm);

    // approx cmax + init exact accumulators; extract candidates; exact scores;
    // exact denominator; finalize; sparse output.
    col_finish<<<(BATCH * NN) / 256, 256>>>(pm, cmax, ck, cs);
    extract<<<(BATCH * NN) / 8, 256>>>(sbf, cmax, cnt, ent);
    recompute<<<BATCH * NN, 256>>>(q, X, cnt, ent, ck);
    colsum_pass<<<(BATCH * NN) / 8, 256>>>(cnt, ent, ck, cs);
    finalize_cols<<<(BATCH * NN) / 256, 256>>>(ck, cs, cmax, csum);
    {
        const int smemS = 256 * 17 * 4 + 256;
        spmm_out<<<dim3(128, BATCH), 256, smemS>>>(xt, cnt, ent, cmax, csum, out);
    }
}

// round 16
// speedup vs baseline: 1.0355x; 1.0355x over previous
#include <cuda_runtime.h>
#include <cuda_bf16.h>
#include <cuda_fp16.h>
#include <cstdint>

#define BATCH 8
#define NN 2048
#define EE 2048

#define BM 256
#define BN 128
#define STAGES 4
#define STAGE_BYTES 49152       // A: 256x128B (32KB) + B: 128x128B (16KB)
#define STAT_BYTES 2048         // 512 x float column-max scratch
#define CAP 2048                // per-row sparse capacity (cannot overflow)
#define ECH 64                  // spmm entry-chunk per pass
#define MG  16                  // spmm m-group

// ---------------- scratch globals (no cudaMalloc allowed) ----------------
__device__ __align__(256) __nv_bfloat16 g_xh[(size_t)BATCH * NN * EE];
__device__ __align__(256) __nv_bfloat16 g_xl[(size_t)BATCH * NN * EE];
__device__ __align__(256) __half        g_xt[(size_t)BATCH * NN * EE];   // X^T per batch [e][n], fp16
__device__ __align__(256) __nv_bfloat16 g_wh[(size_t)EE * EE];
__device__ __align__(256) __nv_bfloat16 g_wl[(size_t)EE * EE];
__device__ __align__(256) __nv_bfloat16 g_qh[(size_t)BATCH * NN * EE];
__device__ __align__(256) __nv_bfloat16 g_ql[(size_t)BATCH * NN * EE];
__device__ __align__(256) __nv_bfloat16 g_s [(size_t)BATCH * NN * NN];   // approx scores (bf16)
__device__ __align__(256) float         g_pm[BATCH * 8 * NN];
__device__ __align__(256) float         g_cmax[BATCH * NN];    // approx col max
__device__ __align__(256) unsigned      g_ck[BATCH * NN];      // encoded exact col max
__device__ __align__(256) float         g_cs[BATCH * NN];      // exact col sum
__device__ __align__(256) int           g_cnt[BATCH * NN];
__device__ __align__(256) uint2         g_ent[(size_t)BATCH * NN * CAP]; // (e, score bits)

// ---------------- helpers ----------------
__device__ __forceinline__ uint32_t smem_u32(const void* p) {
    uint32_t a;
    asm("{ .reg .u64 t; cvta.to.shared.u64 t, %1; cvt.u32.u64 %0, t; }" : "=r"(a) : "l"(p));
    return a;
}
__device__ __forceinline__ void cp16(uint32_t s, const void* g) {
    asm volatile("cp.async.cg.shared.global [%0], [%1], 16;" :: "r"(s), "l"(g) : "memory");
}
__device__ __forceinline__ void cp_commit() {
    asm volatile("cp.async.commit_group;" ::: "memory");
}
template <int N> __device__ __forceinline__ void cp_wait() {
    asm volatile("cp.async.wait_group %0;" :: "n"(N) : "memory");
}
__device__ __forceinline__ void ldm4(uint32_t* r, uint32_t a) {
    asm volatile("ldmatrix.sync.aligned.m8n8.x4.shared.b16 {%0,%1,%2,%3}, [%4];"
                 : "=r"(r[0]), "=r"(r[1]), "=r"(r[2]), "=r"(r[3]) : "r"(a));
}
__device__ __forceinline__ void mma16816(float* c, const uint32_t* a, uint32_t b0, uint32_t b1) {
    asm volatile(
        "mma.sync.aligned.m16n8k16.row.col.f32.bf16.bf16.f32 "
        "{%0,%1,%2,%3}, {%4,%5,%6,%7}, {%8,%9}, {%0,%1,%2,%3};"
        : "+f"(c[0]), "+f"(c[1]), "+f"(c[2]), "+f"(c[3])
        : "r"(a[0]), "r"(a[1]), "r"(a[2]), "r"(a[3]), "r"(b0), "r"(b1));
}
// monotonic float<->uint for atomicMax over signed floats
__device__ __forceinline__ unsigned fenc(float f) {
    unsigned u = __float_as_uint(f);
    return (u & 0x80000000u) ? ~u : (u | 0x80000000u);
}
__device__ __forceinline__ float fdec(unsigned u) {
    u = (u & 0x80000000u) ? (u & 0x7FFFFFFFu) : ~u;
    return __uint_as_float(u);
}

// ---------------- persistent tensor-core GEMM: C tiles 256x128 = A @ B^T ----------------
// NBK=96: 3-phase bf16 split (Ah,Bh)/(Al,Bh)/(Ah,Bl).  NBK=32: 1-phase (Ah,Bh).
// MODE 1: split-store hi/lo bf16 to outH/outL.  MODE 2: bf16(out) to outH only.
// STATS: fused per-tile column MAX (for candidate thresholding).
template <int MODE, bool STATS, int NBK>
__global__ __launch_bounds__(256, 1)
void gemm_mma(const void* Ahv, const void* Alv, const void* Bhv, const void* Blv,
              long long aBatch, long long bBatch, long long cBatch,
              __nv_bfloat16* outH, __nv_bfloat16* outL,
              int gx, int gy, int nTiles, float* pm)
{
    extern __shared__ __align__(128) char smem[];
    const uint32_t stg0 = smem_u32(smem);
    const int tid  = threadIdx.x;
    const int lane = tid & 31;
    const int warp = tid >> 5;

    const int lr = tid >> 3;
    const int lc = tid & 7;
    const uint32_t so = (uint32_t)(lr * 128 + ((lc ^ (lr & 7)) << 4));

    const int wm  = warp & 3;
    const int wn  = warp >> 2;
    const int m0w = wm * 64;
    const int n0w = wn * 64;
    const uint32_t aRow  = (uint32_t)(m0w + (lane & 15));
    const uint32_t aBase = aRow * 128;
    const uint32_t aXor  = aRow & 7;
    const uint32_t ac0   = (uint32_t)(lane >> 4);
    const uint32_t bRow  = (uint32_t)(n0w + ((lane >> 4) << 3) + (lane & 7));
    const uint32_t bBase = 32768u + bRow * 128;
    const uint32_t bXor  = (uint32_t)(lane & 7);
    const uint32_t bc0   = (uint32_t)((lane >> 3) & 1);

    float acc[4][8][4] = {};
    uint32_t af[2][4][4], bf[2][4][4];

    const char *gAh, *gAl, *gBh, *gBl;
    auto setLoad = [&](int t) {
        const int bx = t % gx;
        const int r2 = t / gx;
        const int by = r2 % gy;
        const int bz = r2 / gy;
        const size_t aoff = ((size_t)bz * (size_t)aBatch + (size_t)(by * BM + lr) * EE) * 2 + lc * 16;
        const size_t boff = ((size_t)bz * (size_t)bBatch + (size_t)(bx * BN + lr) * EE) * 2 + lc * 16;
        gAh = (const char*)Ahv + aoff;
        gAl = (const char*)Alv + aoff;
        gBh = (const char*)Bhv + boff;
        gBl = (const char*)Blv + boff;
    };

    auto load_chunk = [&](int s, int kbn, int part) {
        const int p = kbn >> 5;
        const char* a = (p == 1) ? gAl : gAh;
        const char* b = (p == 2) ? gBl : gBh;
        const uint32_t koff = (uint32_t)(kbn & 31) * 128;
        const uint32_t dstA = stg0 + (uint32_t)s * STAGE_BYTES + so;
        const uint32_t dstB = dstA + 32768u;
        cp16(dstA + (uint32_t)(part * 2)     * 4096u, a + koff + (size_t)(part * 2)     * 131072);
        cp16(dstA + (uint32_t)(part * 2 + 1) * 4096u, a + koff + (size_t)(part * 2 + 1) * 131072);
        cp16(dstB + (uint32_t)part           * 4096u, b + koff + (size_t)part           * 131072);
        if (part == 3) cp_commit();
    };
    auto ldm_ks = [&](uint32_t sb_, uint32_t ke, int bsel) {
#pragma unroll
        for (int mt = 0; mt < 4; mt++)
            ldm4(af[bsel][mt], sb_ + aBase + mt * 2048u + (((ke * 2 + ac0) ^ aXor) << 4));
#pragma unroll
        for (int np = 0; np < 4; np++)
            ldm4(bf[bsel][np], sb_ + bBase + np * 2048u + (((ke * 2 + bc0) ^ bXor) << 4));
    };

    int t = blockIdx.x;
    if (t >= nTiles) return;
    setLoad(t);
#pragma unroll
    for (int st = 0; st < 3; st++)
        for (int part = 0; part < 4; part++) load_chunk(st, st, part);
    cp_wait<1>();
    __syncthreads();
    ldm_ks(stg0, 0, 0);

    for (;;) {
        const int bx = t % gx;
        const int r2 = t / gx;
        const int row0 = (r2 % gy) * BM;
        const int col0 = bx * BN;
        const int z    = r2 / gy;
        const bool hasNext = (t + (int)gridDim.x) < nTiles;

        for (int kb = 0; kb < NBK; kb++) {
            if (kb == NBK - 3 && hasNext) setLoad(t + (int)gridDim.x);
            const bool doLoad = (kb < NBK - 3) || hasNext;
            const int  kbn    = (kb + 3 < NBK) ? (kb + 3) : (kb + 3 - NBK);
            const uint32_t sb = stg0 + (uint32_t)(kb & 3) * STAGE_BYTES;
#pragma unroll
            for (int ks = 0; ks < 4; ks++) {
                if (doLoad) load_chunk((kb + 3) & 3, kbn, ks);
                const int cur = ks & 1;
                if (ks < 3)
                    ldm_ks(sb, (uint32_t)ks + 1, cur ^ 1);
                else if (kb + 1 < NBK)
                    ldm_ks(stg0 + (uint32_t)((kb + 1) & 3) * STAGE_BYTES, 0, cur ^ 1);
#pragma unroll
                for (int mt = 0; mt < 4; mt++)
#pragma unroll
                    for (int np = 0; np < 4; np++) {
                        mma16816(acc[mt][np * 2],     af[cur][mt], bf[cur][np][0], bf[cur][np][1]);
                        mma16816(acc[mt][np * 2 + 1], af[cur][mt], bf[cur][np][2], bf[cur][np][3]);
                    }
            }
            if (kb + 1 < NBK) {
                if (doLoad) cp_wait<1>(); else cp_wait<0>();
                __syncthreads();
            }
        }
        if (hasNext) cp_wait<1>(); else cp_wait<0>();
        __syncthreads();
        if (hasNext) ldm_ks(stg0, 0, 0);

        // -------- epilogue --------
        const int g  = lane >> 2;
        const int tg = lane & 3;
#pragma unroll
        for (int mt = 0; mt < 4; mt++) {
            const int rg = row0 + m0w + mt * 16 + g;
#pragma unroll
            for (int nt = 0; nt < 8; nt++) {
                const int cg = col0 + n0w + nt * 8 + 2 * tg;
                __nv_bfloat16* hb = outH + (size_t)z * (size_t)cBatch;
                if (MODE == 1) {
                    __nv_bfloat16* lb = outL + (size_t)z * (size_t)cBatch;
                    float v[4] = {acc[mt][nt][0], acc[mt][nt][1], acc[mt][nt][2], acc[mt][nt][3]};
                    __nv_bfloat16 h0 = __float2bfloat16(v[0]), h1 = __float2bfloat16(v[1]);
                    __nv_bfloat16 h2 = __float2bfloat16(v[2]), h3 = __float2bfloat16(v[3]);
                    *(__nv_bfloat162*)(hb + (size_t)rg * 2048 + cg)       = __nv_bfloat162(h0, h1);
                    *(__nv_bfloat162*)(hb + (size_t)(rg + 8) * 2048 + cg) = __nv_bfloat162(h2, h3);
                    *(__nv_bfloat162*)(lb + (size_t)rg * 2048 + cg) =
                        __nv_bfloat162(__float2bfloat16(v[0] - __bfloat162float(h0)),
                                       __float2bfloat16(v[1] - __bfloat162float(h1)));
                    *(__nv_bfloat162*)(lb + (size_t)(rg + 8) * 2048 + cg) =
                        __nv_bfloat162(__float2bfloat16(v[2] - __bfloat162float(h2)),
                                       __float2bfloat16(v[3] - __bfloat162float(h3)));
                } else {
                    *(__nv_bfloat162*)(hb + (size_t)rg * 2048 + cg) =
                        __nv_bfloat162(__float2bfloat16(acc[mt][nt][0]), __float2bfloat16(acc[mt][nt][1]));
                    *(__nv_bfloat162*)(hb + (size_t)(rg + 8) * 2048 + cg) =
                        __nv_bfloat162(__float2bfloat16(acc[mt][nt][2]), __float2bfloat16(acc[mt][nt][3]));
                }
            }
        }
        if (STATS) {
            float* sst = (float*)(smem + STAGES * STAGE_BYTES);
#pragma unroll
            for (int nt = 0; nt < 8; nt++) {
#pragma unroll
                for (int p = 0; p < 2; p++) {
                    float m = acc[0][nt][p];
#pragma unroll
                    for (int mt = 0; mt < 4; mt++) {
                        m = fmaxf(m, acc[mt][nt][p]);
                        m = fmaxf(m, acc[mt][nt][2 + p]);
                    }
#pragma unroll
                    for (int off = 4; off < 32; off <<= 1)
                        m = fmaxf(m, __shfl_xor_sync(0xffffffffu, m, off));
                    if (lane < 4) {
                        const int colLocal = n0w + nt * 8 + lane * 2 + p;
                        sst[colLocal * 4 + wm] = m;
                    }
                }
            }
            __syncthreads();
            if (tid < 128) {
                float M = fmaxf(fmaxf(sst[tid * 4 + 0], sst[tid * 4 + 1]),
                                fmaxf(sst[tid * 4 + 2], sst[tid * 4 + 3]));
                const size_t o = ((size_t)z * (size_t)gy + (size_t)(row0 / BM)) * NN
                               + (size_t)(col0 + tid);
                pm[o] = M;
            }
            __syncthreads();
        }
        if (!hasNext) break;
#pragma unroll
        for (int mt = 0; mt < 4; mt++)
#pragma unroll
            for (int nt = 0; nt < 8; nt++)
#pragma unroll
                for (int q = 0; q < 4; q++) acc[mt][nt][q] = 0.0f;
        t += (int)gridDim.x;
    }
}

// ---------------- fused prep: X -> (bf16 hi/lo + fp16 transpose), W -> bf16 hi/lo ----------------
__global__ __launch_bounds__(256)
void prep(const float* __restrict__ X, const float* __restrict__ W,
          __nv_bfloat16* __restrict__ xh, __nv_bfloat16* __restrict__ xl,
          __half* __restrict__ xt,
          __nv_bfloat16* __restrict__ wh, __nv_bfloat16* __restrict__ wl)
{
    const int c  = threadIdx.x & 31;
    const int r0 = threadIdx.x >> 5;
    const int e0 = blockIdx.x * 32;
    const int n0 = blockIdx.y * 32;
    if (blockIdx.z == 8) {
#pragma unroll
        for (int k = 0; k < 4; k++) {
            const int r = r0 + k * 8;
            const size_t i = (size_t)(n0 + r) * EE + e0 + c;
            const float v = W[i];
            const __nv_bfloat16 h = __float2bfloat16(v);
            wh[i] = h;
            wl[i] = __float2bfloat16(v - __bfloat162float(h));
        }
        return;
    }
    __shared__ float tile[32][33];
    const int b = blockIdx.z;
    const float* Xb  = X  + (size_t)b * NN * EE;
    __half*      xtb = xt + (size_t)b * NN * EE;
#pragma unroll
    for (int k = 0; k < 4; k++) {
        const int r = r0 + k * 8;
        const size_t i = (size_t)(n0 + r) * EE + e0 + c;
        const float v = Xb[i];
        tile[r][c] = v;
        const __nv_bfloat16 h = __float2bfloat16(v);
        xh[(size_t)b * NN * EE + i] = h;
        xl[(size_t)b * NN * EE + i] = __float2bfloat16(v - __bfloat162float(h));
    }
    __syncthreads();
#pragma unroll
    for (int k = 0; k < 4; k++) {
        const int r = r0 + k * 8;
        xtb[(size_t)(e0 + r) * NN + n0 + c] = __float2half(tile[c][r]);
    }
}

// ---------------- combine approx per-tile maxes -> approx cmax; init exact accumulators ----
__global__ void col_finish(const float* __restrict__ pm, float* __restrict__ cmax,
                           unsigned* __restrict__ ck, float* __restrict__ cs)
{
    const int i = blockIdx.x * blockDim.x + threadIdx.x;
    const int b = i >> 11, col = i & 2047;
    const float* pmb = pm + (size_t)b * 8 * NN + col;
    float M = pmb[0];
#pragma unroll
    for (int t2 = 1; t2 < 8; t2++) M = fmaxf(M, pmb[(size_t)t2 * NN]);
    cmax[i] = M;
    ck[i] = 0u;      // encoded -inf
    cs[i] = 0.0f;
}

// ---------------- fused candidate extraction + exact recompute (block per row) ----------
// Threshold on approx bf16 scores at -21.5 (error << margin; dropped weight < e^-20).
// Exact q = float(qh)+float(ql) built in smem (residual 2^-18); warp-per-candidate dot.
__global__ __launch_bounds__(256)
void extract_recompute(const __nv_bfloat16* __restrict__ S, const float* __restrict__ cmax,
                       const __nv_bfloat16* __restrict__ qh, const __nv_bfloat16* __restrict__ ql,
                       const float* __restrict__ X,
                       int* __restrict__ cnt, uint2* __restrict__ ent,
                       unsigned* __restrict__ ck)
{
    extern __shared__ __align__(16) char dsm[];
    float* qs    = (float*)dsm;                    // [2048] 8KB
    int (*seg)[256] = (int (*)[256])(dsm + 8192);  // [8][256] 8KB
    int*   scand = (int*)(dsm + 16384);            // [2048] 8KB
    int*   scnt2 = (int*)(dsm + 24576);            // [8]
    int*   soff  = scnt2 + 8;                      // [8]
    int*   stot  = soff + 8;

    const int row  = blockIdx.x;                   // b*NN + m
    const int tid  = threadIdx.x;
    const int lane = tid & 31;
    const int w    = tid >> 5;                     // 0..7
    const int b    = row >> 11;

    // build exact q row in smem
    {
        const __nv_bfloat16* qhr = qh + (size_t)row * EE;
        const __nv_bfloat16* qlr = ql + (size_t)row * EE;
#pragma unroll
        for (int i = 0; i < 8; i++) {
            const int j = tid + i * 256;
            qs[j] = __bfloat162float(qhr[j]) + __bfloat162float(qlr[j]);
        }
    }

    // phase A: each warp scans its 256 columns, ballot-compacts candidate indices
    {
        const __nv_bfloat16* Srow = S + (size_t)row * NN;
        const float* cmb = cmax + b * NN;
        int count = 0;
#pragma unroll
        for (int i = 0; i < 8; i++) {
            const int j = w * 256 + i * 32 + lane;
            const float v = __bfloat162float(Srow[j]);
            const bool keep = (v - cmb[j]) > -21.5f;
            const unsigned bal = __ballot_sync(0xffffffffu, keep);
            if (keep) seg[w][count + __popc(bal & ((1u << lane) - 1u))] = j;
            count += __popc(bal);
        }
        if (lane == 0) scnt2[w] = count;
    }
    __syncthreads();

    // prefix offsets
    if (tid == 0) {
        int acc2 = 0;
#pragma unroll
        for (int i = 0; i < 8; i++) { soff[i] = acc2; acc2 += scnt2[i]; }
        *stot = acc2;
        cnt[row] = acc2;
    }
    __syncthreads();

    // phase B: compact into scand
    for (int k = lane; k < scnt2[w]; k += 32) scand[soff[w] + k] = seg[w][k];
    __syncthreads();

    // phase C: warp per candidate — exact fp32 dot q . X[e]
    const int total = *stot;
    const float* Xb = X + (size_t)b * NN * EE;
    uint2* re = ent + (size_t)row * CAP;
    for (int idx = w; idx < total; idx += 8) {
        const int e = scand[idx];
        const float4* xr = (const float4*)(Xb + (size_t)e * EE);
        float sum = 0.0f;
#pragma unroll
        for (int i = 0; i < 16; i++) {
            const float4 a  = ((const float4*)qs)[lane + i * 32];
            const float4 x4 = __ldg(xr + lane + i * 32);
            sum += a.x * x4.x + a.y * x4.y + a.z * x4.z + a.w * x4.w;
        }
#pragma unroll
        for (int off = 16; off; off >>= 1) sum += __shfl_xor_sync(0xffffffffu, sum, off);
        if (lane == 0) {
            re[idx] = make_uint2((unsigned)e, __float_as_uint(sum));
            atomicMax(&ck[b * NN + e], fenc(sum));
        }
    }
}

// ---------------- column denominator over candidates (exact scores) ----------------
__global__ __launch_bounds__(256)
void colsum_pass(const int* __restrict__ cnt, const uint2* __restrict__ ent,
                 const unsigned* __restrict__ ck, float* __restrict__ cs)
{
    const int gw   = blockIdx.x * 8 + (threadIdx.x >> 5);
    const int lane = threadIdx.x & 31;
    const int b = gw >> 11;
    const int c = cnt[gw];
    const uint2* re = ent + (size_t)gw * CAP;
    for (int idx = lane; idx < c; idx += 32) {
        const uint2 p = re[idx];
        const int be = b * NN + (int)p.x;
        atomicAdd(&cs[be], __expf(__uint_as_float(p.y) - fdec(ck[be])));
    }
}

// ---------------- sparse output: out[b,n,m] = sum_e w[m,e] * xt[b,e,n] ----------------
// Weight computed inline from exact (score, col-max key, col-sum): finalize fused.
__global__ __launch_bounds__(256)
void spmm_out(const __half* __restrict__ xt, const int* __restrict__ cnt,
              const uint2* __restrict__ ent,
              const unsigned* __restrict__ ck, const float* __restrict__ cs,
              float* __restrict__ out)
{
    extern __shared__ __align__(16) char dsm[];
    uint2 (*sent)[ECH] = (uint2 (*)[ECH])dsm;            // [MG][ECH] = 8KB
    int*   scnt        = (int*)(dsm + MG * ECH * 8);     // [MG]
    float (*buf)[17]   = (float (*)[17])dsm;             // write staging (reuses dsm)

    const int mg = blockIdx.x;
    const int b  = blockIdx.y;
    const int m0 = mg * MG;
    const int tid = threadIdx.x;
    const __half* xtb = xt + (size_t)b * NN * EE;
    float* outb = out + (size_t)b * NN * NN;

    if (tid < MG) scnt[tid] = cnt[b * NN + m0 + tid];
    __syncthreads();
    int maxc = 0;
#pragma unroll
    for (int j = 0; j < MG; j++) maxc = max(maxc, scnt[j]);

    float acc[8][MG];
#pragma unroll
    for (int k = 0; k < 8; k++)
#pragma unroll
        for (int j = 0; j < MG; j++) acc[k][j] = 0.0f;

    const int passes = (maxc + ECH - 1) / ECH;
    for (int pass = 0; pass < passes; pass++) {
        const int srow  = tid >> 4;
        const int base  = pass * ECH;
        const int avail = min(scnt[srow] - base, ECH);
#pragma unroll
        for (int s2 = 0; s2 < ECH / 16; s2++) {
            const int slot = (tid & 15) + s2 * 16;
            if (slot < avail) {
                uint2 p = ent[(size_t)(b * NN + m0 + srow) * CAP + base + slot];
                const int be = b * NN + (int)p.x;
                const float w = __expf(__uint_as_float(p.y) - fdec(__ldg(ck + be))) / __ldg(cs + be);
                sent[srow][slot] = make_uint2(p.x, __float_as_uint(w));
            }
        }
        __syncthreads();
#pragma unroll
        for (int j = 0; j < MG; j++) {
            const int cj = min(scnt[j] - base, ECH);
            for (int idx = 0; idx < cj; idx++) {
                const uint2 p = sent[j][idx];
                const float w = __uint_as_float(p.y);
                const __half* xr = xtb + (size_t)p.x * NN + tid;
#pragma unroll
                for (int k = 0; k < 8; k++)
                    acc[k][j] = fmaf(w, __half2float(__ldg(xr + k * 256)), acc[k][j]);
            }
        }
        __syncthreads();
    }

#pragma unroll
    for (int k = 0; k < 8; k++) {
        __syncthreads();
#pragma unroll
        for (int j = 0; j < MG; j++) buf[tid][j] = acc[k][j];
        __syncthreads();
#pragma unroll
        for (int s2 = 0; s2 < 4; s2++) {
            const int lin = s2 * 256 + tid;
            const int r   = lin >> 2;
            const int c4  = (lin & 3) * 4;
            const int n   = k * 256 + r;
            *(float4*)(outb + (size_t)n * NN + m0 + c4) =
                make_float4(buf[r][c4], buf[r][c4 + 1], buf[r][c4 + 2], buf[r][c4 + 3]);
        }
    }
}

// ---------------- launch ----------------
extern "C" void kernel_launch(void* const* d_in, const int* in_sizes, int n_in,
                              void* d_out, int out_size)
{
    const float* X = (const float*)d_in[0];
    const float* W = (const float*)d_in[1];
    // d_in[2] = bias: per-column constant on scores -> cancels in axis-1 softmax.
    // d_in[3] = gamma: scalar constant -> cancels likewise. Both unused.
    float* out = (float*)d_out;

    __nv_bfloat16 *xh, *xl, *wh, *wl, *qh, *ql, *sbf;
    __half *xt;
    float *pm, *cmax, *cs;
    unsigned *ck;
    int *cnt; uint2 *ent;
    cudaGetSymbolAddress((void**)&xh, g_xh);  cudaGetSymbolAddress((void**)&xl, g_xl);
    cudaGetSymbolAddress((void**)&xt, g_xt);
    cudaGetSymbolAddress((void**)&wh, g_wh);  cudaGetSymbolAddress((void**)&wl, g_wl);
    cudaGetSymbolAddress((void**)&qh, g_qh);  cudaGetSymbolAddress((void**)&ql, g_ql);
    cudaGetSymbolAddress((void**)&sbf, g_s);
    cudaGetSymbolAddress((void**)&pm, g_pm);
    cudaGetSymbolAddress((void**)&cmax, g_cmax);
    cudaGetSymbolAddress((void**)&ck, g_ck);  cudaGetSymbolAddress((void**)&cs, g_cs);
    cudaGetSymbolAddress((void**)&cnt, g_cnt);
    cudaGetSymbolAddress((void**)&ent, g_ent);

    int dev = 0;  cudaGetDevice(&dev);
    int nsm = 148;
    cudaDeviceGetAttribute(&nsm, cudaDevAttrMultiProcessorCount, dev);

    const int smemG = STAGES * STAGE_BYTES + STAT_BYTES;
    cudaFuncSetAttribute((const void*)gemm_mma<1, false, 96>, cudaFuncAttributeMaxDynamicSharedMemorySize, smemG);
    cudaFuncSetAttribute((const void*)gemm_mma<2, true, 32>,  cudaFuncAttributeMaxDynamicSharedMemorySize, smemG);

    // prep: X -> xh/xl/xt, W -> wh/wl
    prep<<<dim3(64, 64, 9), 256>>>(X, W, xh, xl, xt, wh, wl);

    const long long sXE = (long long)NN * EE;
    const long long sNN = (long long)NN * NN;

    // GEMM1: Q = X W^T. 3-phase bf16 -> hi/lo bf16 (qh, ql).
    gemm_mma<1, false, 96><<<nsm, 256, smemG>>>(xh, xl, wh, wl, 0, 0, 0,
                                                qh, ql, 16, 64, 1024, nullptr);

    // GEMM2: approx S[b] = Qh[b] Xh[b]^T. 1-phase bf16 -> bf16 S + fused col-max.
    gemm_mma<2, true, 32><<<nsm, 256, smemG>>>(qh, qh, xh, xh, sXE, sXE, sNN,
                                               sbf, nullptr, 16, 8, 1024, pm);

    // approx cmax + init; fused extract+exact-recompute; denominator; sparse output.
    col_finish<<<(BATCH * NN) / 256, 256>>>(pm, cmax, ck, cs);
    {
        const int smemE = 8192 * 3 + 128;
        extract_recompute<<<BATCH * NN, 256, smemE>>>(sbf, cmax, qh, ql, X, cnt, ent, ck);
    }
    colsum_pass<<<(BATCH * NN) / 8, 256>>>(cnt, ent, ck, cs);
    {
        const int smemS = 256 * 17 * 4 + 256;
        spmm_out<<<dim3(128, BATCH), 256, smemS>>>(xt, cnt, ent, ck, cs, out);
    }
}

// round 17
// speedup vs baseline: 1.0584x; 1.0220x over previous
#include <cuda_runtime.h>
#include <cuda_bf16.h>
#include <cuda_fp16.h>
#include <cstdint>

#define BATCH 8
#define NN 2048
#define EE 2048

#define BM 256
#define BN 128
#define STAGES 4
#define STAGE_BYTES 49152       // A: 256x128B (32KB) + B: 128x128B (16KB)
#define STAT_BYTES 2048         // 512 x float column-max scratch
#define CAP 2048                // per-row sparse capacity (cannot overflow)
#define ECH 64                  // spmm entry-chunk per pass
#define MG  16                  // spmm m-group

// ---------------- scratch globals (no cudaMalloc allowed) ----------------
__device__ __align__(256) __nv_bfloat16 g_xh[(size_t)BATCH * NN * EE];
__device__ __align__(256) __nv_bfloat16 g_xl[(size_t)BATCH * NN * EE];
__device__ __align__(256) __half        g_xt[(size_t)BATCH * NN * EE];   // X^T per batch [e][n], fp16
__device__ __align__(256) __nv_bfloat16 g_wh[(size_t)EE * EE];
__device__ __align__(256) __nv_bfloat16 g_wl[(size_t)EE * EE];
__device__ __align__(256) __nv_bfloat16 g_qh[(size_t)BATCH * NN * EE];
__device__ __align__(256) __nv_bfloat16 g_ql[(size_t)BATCH * NN * EE];
__device__ __align__(256) __nv_bfloat16 g_s [(size_t)BATCH * NN * NN];   // approx scores (bf16)
__device__ __align__(256) float         g_pm[BATCH * 8 * NN];
__device__ __align__(256) float         g_cmax[BATCH * NN];    // approx col max (softmax reference)
__device__ __align__(256) float         g_cs[BATCH * NN];      // exact col sum (vs approx ref)
__device__ __align__(256) int           g_cnt[BATCH * NN];
__device__ __align__(256) uint2         g_ent[(size_t)BATCH * NN * CAP]; // (e, exact score bits)

// ---------------- helpers ----------------
__device__ __forceinline__ uint32_t smem_u32(const void* p) {
    uint32_t a;
    asm("{ .reg .u64 t; cvta.to.shared.u64 t, %1; cvt.u32.u64 %0, t; }" : "=r"(a) : "l"(p));
    return a;
}
__device__ __forceinline__ void cp16(uint32_t s, const void* g) {
    asm volatile("cp.async.cg.shared.global [%0], [%1], 16;" :: "r"(s), "l"(g) : "memory");
}
__device__ __forceinline__ void cp_commit() {
    asm volatile("cp.async.commit_group;" ::: "memory");
}
template <int N> __device__ __forceinline__ void cp_wait() {
    asm volatile("cp.async.wait_group %0;" :: "n"(N) : "memory");
}
__device__ __forceinline__ void ldm4(uint32_t* r, uint32_t a) {
    asm volatile("ldmatrix.sync.aligned.m8n8.x4.shared.b16 {%0,%1,%2,%3}, [%4];"
                 : "=r"(r[0]), "=r"(r[1]), "=r"(r[2]), "=r"(r[3]) : "r"(a));
}
__device__ __forceinline__ void mma16816(float* c, const uint32_t* a, uint32_t b0, uint32_t b1) {
    asm volatile(
        "mma.sync.aligned.m16n8k16.row.col.f32.bf16.bf16.f32 "
        "{%0,%1,%2,%3}, {%4,%5,%6,%7}, {%8,%9}, {%0,%1,%2,%3};"
        : "+f"(c[0]), "+f"(c[1]), "+f"(c[2]), "+f"(c[3])
        : "r"(a[0]), "r"(a[1]), "r"(a[2]), "r"(a[3]), "r"(b0), "r"(b1));
}

// ---------------- persistent tensor-core GEMM: C tiles 256x128 = A @ B^T ----------------
// NBK=96: 3-phase bf16 split (Ah,Bh)/(Al,Bh)/(Ah,Bl).  NBK=32: 1-phase (Ah,Bh).
// MODE 1: split-store hi/lo bf16 to outH/outL.  MODE 2: bf16(out) to outH only.
// STATS: fused per-tile column MAX (softmax reference / candidate thresholding).
template <int MODE, bool STATS, int NBK>
__global__ __launch_bounds__(256, 1)
void gemm_mma(const void* Ahv, const void* Alv, const void* Bhv, const void* Blv,
              long long aBatch, long long bBatch, long long cBatch,
              __nv_bfloat16* outH, __nv_bfloat16* outL,
              int gx, int gy, int nTiles, float* pm)
{
    extern __shared__ __align__(128) char smem[];
    const uint32_t stg0 = smem_u32(smem);
    const int tid  = threadIdx.x;
    const int lane = tid & 31;
    const int warp = tid >> 5;

    const int lr = tid >> 3;
    const int lc = tid & 7;
    const uint32_t so = (uint32_t)(lr * 128 + ((lc ^ (lr & 7)) << 4));

    const int wm  = warp & 3;
    const int wn  = warp >> 2;
    const int m0w = wm * 64;
    const int n0w = wn * 64;
    const uint32_t aRow  = (uint32_t)(m0w + (lane & 15));
    const uint32_t aBase = aRow * 128;
    const uint32_t aXor  = aRow & 7;
    const uint32_t ac0   = (uint32_t)(lane >> 4);
    const uint32_t bRow  = (uint32_t)(n0w + ((lane >> 4) << 3) + (lane & 7));
    const uint32_t bBase = 32768u + bRow * 128;
    const uint32_t bXor  = (uint32_t)(lane & 7);
    const uint32_t bc0   = (uint32_t)((lane >> 3) & 1);

    float acc[4][8][4] = {};
    uint32_t af[2][4][4], bf[2][4][4];

    const char *gAh, *gAl, *gBh, *gBl;
    auto setLoad = [&](int t) {
        const int bx = t % gx;
        const int r2 = t / gx;
        const int by = r2 % gy;
        const int bz = r2 / gy;
        const size_t aoff = ((size_t)bz * (size_t)aBatch + (size_t)(by * BM + lr) * EE) * 2 + lc * 16;
        const size_t boff = ((size_t)bz * (size_t)bBatch + (size_t)(bx * BN + lr) * EE) * 2 + lc * 16;
        gAh = (const char*)Ahv + aoff;
        gAl = (const char*)Alv + aoff;
        gBh = (const char*)Bhv + boff;
        gBl = (const char*)Blv + boff;
    };

    auto load_chunk = [&](int s, int kbn, int part) {
        const int p = kbn >> 5;
        const char* a = (p == 1) ? gAl : gAh;
        const char* b = (p == 2) ? gBl : gBh;
        const uint32_t koff = (uint32_t)(kbn & 31) * 128;
        const uint32_t dstA = stg0 + (uint32_t)s * STAGE_BYTES + so;
        const uint32_t dstB = dstA + 32768u;
        cp16(dstA + (uint32_t)(part * 2)     * 4096u, a + koff + (size_t)(part * 2)     * 131072);
        cp16(dstA + (uint32_t)(part * 2 + 1) * 4096u, a + koff + (size_t)(part * 2 + 1) * 131072);
        cp16(dstB + (uint32_t)part           * 4096u, b + koff + (size_t)part           * 131072);
        if (part == 3) cp_commit();
    };
    auto ldm_ks = [&](uint32_t sb_, uint32_t ke, int bsel) {
#pragma unroll
        for (int mt = 0; mt < 4; mt++)
            ldm4(af[bsel][mt], sb_ + aBase + mt * 2048u + (((ke * 2 + ac0) ^ aXor) << 4));
#pragma unroll
        for (int np = 0; np < 4; np++)
            ldm4(bf[bsel][np], sb_ + bBase + np * 2048u + (((ke * 2 + bc0) ^ bXor) << 4));
    };

    int t = blockIdx.x;
    if (t >= nTiles) return;
    setLoad(t);
#pragma unroll
    for (int st = 0; st < 3; st++)
        for (int part = 0; part < 4; part++) load_chunk(st, st, part);
    cp_wait<1>();
    __syncthreads();
    ldm_ks(stg0, 0, 0);

    for (;;) {
        const int bx = t % gx;
        const int r2 = t / gx;
        const int row0 = (r2 % gy) * BM;
        const int col0 = bx * BN;
        const int z    = r2 / gy;
        const bool hasNext = (t + (int)gridDim.x) < nTiles;

        for (int kb = 0; kb < NBK; kb++) {
            if (kb == NBK - 3 && hasNext) setLoad(t + (int)gridDim.x);
            const bool doLoad = (kb < NBK - 3) || hasNext;
            const int  kbn    = (kb + 3 < NBK) ? (kb + 3) : (kb + 3 - NBK);
            const uint32_t sb = stg0 + (uint32_t)(kb & 3) * STAGE_BYTES;
#pragma unroll
            for (int ks = 0; ks < 4; ks++) {
                if (doLoad) load_chunk((kb + 3) & 3, kbn, ks);
                const int cur = ks & 1;
                if (ks < 3)
                    ldm_ks(sb, (uint32_t)ks + 1, cur ^ 1);
                else if (kb + 1 < NBK)
                    ldm_ks(stg0 + (uint32_t)((kb + 1) & 3) * STAGE_BYTES, 0, cur ^ 1);
#pragma unroll
                for (int mt = 0; mt < 4; mt++)
#pragma unroll
                    for (int np = 0; np < 4; np++) {
                        mma16816(acc[mt][np * 2],     af[cur][mt], bf[cur][np][0], bf[cur][np][1]);
                        mma16816(acc[mt][np * 2 + 1], af[cur][mt], bf[cur][np][2], bf[cur][np][3]);
                    }
            }
            if (kb + 1 < NBK) {
                if (doLoad) cp_wait<1>(); else cp_wait<0>();
                __syncthreads();
            }
        }
        if (hasNext) cp_wait<1>(); else cp_wait<0>();
        __syncthreads();
        if (hasNext) ldm_ks(stg0, 0, 0);

        // -------- epilogue --------
        const int g  = lane >> 2;
        const int tg = lane & 3;
#pragma unroll
        for (int mt = 0; mt < 4; mt++) {
            const int rg = row0 + m0w + mt * 16 + g;
#pragma unroll
            for (int nt = 0; nt < 8; nt++) {
                const int cg = col0 + n0w + nt * 8 + 2 * tg;
                __nv_bfloat16* hb = outH + (size_t)z * (size_t)cBatch;
                if (MODE == 1) {
                    __nv_bfloat16* lb = outL + (size_t)z * (size_t)cBatch;
                    float v[4] = {acc[mt][nt][0], acc[mt][nt][1], acc[mt][nt][2], acc[mt][nt][3]};
                    __nv_bfloat16 h0 = __float2bfloat16(v[0]), h1 = __float2bfloat16(v[1]);
                    __nv_bfloat16 h2 = __float2bfloat16(v[2]), h3 = __float2bfloat16(v[3]);
                    *(__nv_bfloat162*)(hb + (size_t)rg * 2048 + cg)       = __nv_bfloat162(h0, h1);
                    *(__nv_bfloat162*)(hb + (size_t)(rg + 8) * 2048 + cg) = __nv_bfloat162(h2, h3);
                    *(__nv_bfloat162*)(lb + (size_t)rg * 2048 + cg) =
                        __nv_bfloat162(__float2bfloat16(v[0] - __bfloat162float(h0)),
                                       __float2bfloat16(v[1] - __bfloat162float(h1)));
                    *(__nv_bfloat162*)(lb + (size_t)(rg + 8) * 2048 + cg) =
                        __nv_bfloat162(__float2bfloat16(v[2] - __bfloat162float(h2)),
                                       __float2bfloat16(v[3] - __bfloat162float(h3)));
                } else {
                    *(__nv_bfloat162*)(hb + (size_t)rg * 2048 + cg) =
                        __nv_bfloat162(__float2bfloat16(acc[mt][nt][0]), __float2bfloat16(acc[mt][nt][1]));
                    *(__nv_bfloat162*)(hb + (size_t)(rg + 8) * 2048 + cg) =
                        __nv_bfloat162(__float2bfloat16(acc[mt][nt][2]), __float2bfloat16(acc[mt][nt][3]));
                }
            }
        }
        if (STATS) {
            float* sst = (float*)(smem + STAGES * STAGE_BYTES);
#pragma unroll
            for (int nt = 0; nt < 8; nt++) {
#pragma unroll
                for (int p = 0; p < 2; p++) {
                    float m = acc[0][nt][p];
#pragma unroll
                    for (int mt = 0; mt < 4; mt++) {
                        m = fmaxf(m, acc[mt][nt][p]);
                        m = fmaxf(m, acc[mt][nt][2 + p]);
                    }
#pragma unroll
                    for (int off = 4; off < 32; off <<= 1)
                        m = fmaxf(m, __shfl_xor_sync(0xffffffffu, m, off));
                    if (lane < 4) {
                        const int colLocal = n0w + nt * 8 + lane * 2 + p;
                        sst[colLocal * 4 + wm] = m;
                    }
                }
            }
            __syncthreads();
            if (tid < 128) {
                float M = fmaxf(fmaxf(sst[tid * 4 + 0], sst[tid * 4 + 1]),
                                fmaxf(sst[tid * 4 + 2], sst[tid * 4 + 3]));
                const size_t o = ((size_t)z * (size_t)gy + (size_t)(row0 / BM)) * NN
                               + (size_t)(col0 + tid);
                pm[o] = M;
            }
            __syncthreads();
        }
        if (!hasNext) break;
#pragma unroll
        for (int mt = 0; mt < 4; mt++)
#pragma unroll
            for (int nt = 0; nt < 8; nt++)
#pragma unroll
                for (int q = 0; q < 4; q++) acc[mt][nt][q] = 0.0f;
        t += (int)gridDim.x;
    }
}

// ---------------- fused prep: X -> (bf16 hi/lo + fp16 transpose), W -> bf16 hi/lo ----------------
__global__ __launch_bounds__(256)
void prep(const float* __restrict__ X, const float* __restrict__ W,
          __nv_bfloat16* __restrict__ xh, __nv_bfloat16* __restrict__ xl,
          __half* __restrict__ xt,
          __nv_bfloat16* __restrict__ wh, __nv_bfloat16* __restrict__ wl)
{
    const int c  = threadIdx.x & 31;
    const int r0 = threadIdx.x >> 5;
    const int e0 = blockIdx.x * 32;
    const int n0 = blockIdx.y * 32;
    if (blockIdx.z == 8) {
#pragma unroll
        for (int k = 0; k < 4; k++) {
            const int r = r0 + k * 8;
            const size_t i = (size_t)(n0 + r) * EE + e0 + c;
            const float v = W[i];
            const __nv_bfloat16 h = __float2bfloat16(v);
            wh[i] = h;
            wl[i] = __float2bfloat16(v - __bfloat162float(h));
        }
        return;
    }
    __shared__ float tile[32][33];
    const int b = blockIdx.z;
    const float* Xb  = X  + (size_t)b * NN * EE;
    __half*      xtb = xt + (size_t)b * NN * EE;
#pragma unroll
    for (int k = 0; k < 4; k++) {
        const int r = r0 + k * 8;
        const size_t i = (size_t)(n0 + r) * EE + e0 + c;
        const float v = Xb[i];
        tile[r][c] = v;
        const __nv_bfloat16 h = __float2bfloat16(v);
        xh[(size_t)b * NN * EE + i] = h;
        xl[(size_t)b * NN * EE + i] = __float2bfloat16(v - __bfloat162float(h));
    }
    __syncthreads();
#pragma unroll
    for (int k = 0; k < 4; k++) {
        const int r = r0 + k * 8;
        xtb[(size_t)(e0 + r) * NN + n0 + c] = __float2half(tile[c][r]);
    }
}

// ---------------- combine approx per-tile maxes -> approx cmax; init col-sum accumulator ----
__global__ void col_finish(const float* __restrict__ pm, float* __restrict__ cmax,
                           float* __restrict__ cs)
{
    const int i = blockIdx.x * blockDim.x + threadIdx.x;
    const int b = i >> 11, col = i & 2047;
    const float* pmb = pm + (size_t)b * 8 * NN + col;
    float M = pmb[0];
#pragma unroll
    for (int t2 = 1; t2 < 8; t2++) M = fmaxf(M, pmb[(size_t)t2 * NN]);
    cmax[i] = M;
    cs[i] = 0.0f;
}

// ---------------- fused candidate extraction + exact recompute + col-sum (block/row) ----
// Threshold on approx bf16 scores at -21.5 (approx error << margin; dropped weight < e^-20).
// Exact q = float(qh)+float(ql) in smem; warp-per-candidate fp32 dot.
// Max-free softmax: denominator accumulated vs APPROX cmax (reference cancels exactly).
__global__ __launch_bounds__(256)
void extract_recompute(const __nv_bfloat16* __restrict__ S, const float* __restrict__ cmax,
                       const __nv_bfloat16* __restrict__ qh, const __nv_bfloat16* __restrict__ ql,
                       const float* __restrict__ X,
                       int* __restrict__ cnt, uint2* __restrict__ ent,
                       float* __restrict__ cs)
{
    extern __shared__ __align__(16) char dsm[];
    float* qs    = (float*)dsm;                    // [2048] 8KB
    int (*seg)[256] = (int (*)[256])(dsm + 8192);  // [8][256] 8KB
    int*   scand = (int*)(dsm + 16384);            // [2048] 8KB
    int*   scnt2 = (int*)(dsm + 24576);            // [8]
    int*   soff  = scnt2 + 8;                      // [8]
    int*   stot  = soff + 8;

    const int row  = blockIdx.x;                   // b*NN + m
    const int tid  = threadIdx.x;
    const int lane = tid & 31;
    const int w    = tid >> 5;                     // 0..7
    const int b    = row >> 11;

    // build exact q row in smem
    {
        const __nv_bfloat16* qhr = qh + (size_t)row * EE;
        const __nv_bfloat16* qlr = ql + (size_t)row * EE;
#pragma unroll
        for (int i = 0; i < 8; i++) {
            const int j = tid + i * 256;
            qs[j] = __bfloat162float(qhr[j]) + __bfloat162float(qlr[j]);
        }
    }

    // phase A: each warp scans its 256 columns, ballot-compacts candidate indices
    {
        const __nv_bfloat16* Srow = S + (size_t)row * NN;
        const float* cmb = cmax + b * NN;
        int count = 0;
#pragma unroll
        for (int i = 0; i < 8; i++) {
            const int j = w * 256 + i * 32 + lane;
            const float v = __bfloat162float(Srow[j]);
            const bool keep = (v - cmb[j]) > -21.5f;
            const unsigned bal = __ballot_sync(0xffffffffu, keep);
            if (keep) seg[w][count + __popc(bal & ((1u << lane) - 1u))] = j;
            count += __popc(bal);
        }
        if (lane == 0) scnt2[w] = count;
    }
    __syncthreads();

    // prefix offsets
    if (tid == 0) {
        int acc2 = 0;
#pragma unroll
        for (int i = 0; i < 8; i++) { soff[i] = acc2; acc2 += scnt2[i]; }
        *stot = acc2;
        cnt[row] = acc2;
    }
    __syncthreads();

    // phase B: compact into scand
    for (int k = lane; k < scnt2[w]; k += 32) scand[soff[w] + k] = seg[w][k];
    __syncthreads();

    // phase C: warp per candidate — exact fp32 dot q . X[e]; accumulate col denominator
    const int total = *stot;
    const float* Xb = X + (size_t)b * NN * EE;
    uint2* re = ent + (size_t)row * CAP;
    for (int idx = w; idx < total; idx += 8) {
        const int e = scand[idx];
        const float4* xr = (const float4*)(Xb + (size_t)e * EE);
        float sum = 0.0f;
#pragma unroll
        for (int i = 0; i < 16; i++) {
            const float4 a  = ((const float4*)qs)[lane + i * 32];
            const float4 x4 = __ldg(xr + lane + i * 32);
            sum += a.x * x4.x + a.y * x4.y + a.z * x4.z + a.w * x4.w;
        }
#pragma unroll
        for (int off = 16; off; off >>= 1) sum += __shfl_xor_sync(0xffffffffu, sum, off);
        if (lane == 0) {
            re[idx] = make_uint2((unsigned)e, __float_as_uint(sum));
            atomicAdd(&cs[b * NN + e], __expf(sum - __ldg(cmax + b * NN + e)));
        }
    }
}

// ---------------- sparse output: out[b,n,m] = sum_e w[m,e] * xt[b,e,n] ----------------
// w = exp(s - cmax_approx)/cs computed inline (reference cancels exactly).
// Thread handles n pairs {512*k2 + 2*tid + p}; half2 loads (4 per entry).
__global__ __launch_bounds__(256)
void spmm_out(const __half* __restrict__ xt, const int* __restrict__ cnt,
              const uint2* __restrict__ ent,
              const float* __restrict__ cmax, const float* __restrict__ cs,
              float* __restrict__ out)
{
    extern __shared__ __align__(16) char dsm[];
    uint2 (*sent)[ECH] = (uint2 (*)[ECH])dsm;            // [MG][ECH] = 8KB
    int*   scnt        = (int*)(dsm + MG * ECH * 8);     // [MG]
    float (*buf)[17]   = (float (*)[17])dsm;             // write staging (reuses dsm)

    const int mg = blockIdx.x;
    const int b  = blockIdx.y;
    const int m0 = mg * MG;
    const int tid = threadIdx.x;
    const __half* xtb = xt + (size_t)b * NN * EE;
    float* outb = out + (size_t)b * NN * NN;

    if (tid < MG) scnt[tid] = cnt[b * NN + m0 + tid];
    __syncthreads();
    int maxc = 0;
#pragma unroll
    for (int j = 0; j < MG; j++) maxc = max(maxc, scnt[j]);

    float acc[8][MG];   // k = k2*2 + p  -> n = 512*k2 + 2*tid + p
#pragma unroll
    for (int k = 0; k < 8; k++)
#pragma unroll
        for (int j = 0; j < MG; j++) acc[k][j] = 0.0f;

    const int passes = (maxc + ECH - 1) / ECH;
    for (int pass = 0; pass < passes; pass++) {
        const int srow  = tid >> 4;
        const int base  = pass * ECH;
        const int avail = min(scnt[srow] - base, ECH);
#pragma unroll
        for (int s2 = 0; s2 < ECH / 16; s2++) {
            const int slot = (tid & 15) + s2 * 16;
            if (slot < avail) {
                uint2 p = ent[(size_t)(b * NN + m0 + srow) * CAP + base + slot];
                const int be = b * NN + (int)p.x;
                const float w = __expf(__uint_as_float(p.y) - __ldg(cmax + be)) / __ldg(cs + be);
                sent[srow][slot] = make_uint2(p.x, __float_as_uint(w));
            }
        }
        __syncthreads();
#pragma unroll
        for (int j = 0; j < MG; j++) {
            const int cj = min(scnt[j] - base, ECH);
            for (int idx = 0; idx < cj; idx++) {
                const uint2 p = sent[j][idx];
                const float w = __uint_as_float(p.y);
                const __half2* xr2 = (const __half2*)(xtb + (size_t)p.x * NN) + tid;
#pragma unroll
                for (int k2 = 0; k2 < 4; k2++) {
                    const float2 f = __half22float2(__ldg(xr2 + k2 * 256));
                    acc[k2 * 2][j]     = fmaf(w, f.x, acc[k2 * 2][j]);
                    acc[k2 * 2 + 1][j] = fmaf(w, f.y, acc[k2 * 2 + 1][j]);
                }
            }
        }
        __syncthreads();
    }

#pragma unroll
    for (int k2 = 0; k2 < 4; k2++)
#pragma unroll
        for (int p = 0; p < 2; p++) {
            __syncthreads();
#pragma unroll
            for (int j = 0; j < MG; j++) buf[tid][j] = acc[k2 * 2 + p][j];
            __syncthreads();
#pragma unroll
            for (int s2 = 0; s2 < 4; s2++) {
                const int lin = s2 * 256 + tid;
                const int r   = lin >> 2;
                const int c4  = (lin & 3) * 4;
                const int n   = 512 * k2 + p + 2 * r;
                *(float4*)(outb + (size_t)n * NN + m0 + c4) =
                    make_float4(buf[r][c4], buf[r][c4 + 1], buf[r][c4 + 2], buf[r][c4 + 3]);
            }
        }
}

// ---------------- launch ----------------
extern "C" void kernel_launch(void* const* d_in, const int* in_sizes, int n_in,
                              void* d_out, int out_size)
{
    const float* X = (const float*)d_in[0];
    const float* W = (const float*)d_in[1];
    // d_in[2] = bias: per-column constant on scores -> cancels in axis-1 softmax.
    // d_in[3] = gamma: scalar constant -> cancels likewise. Both unused.
    float* out = (float*)d_out;

    __nv_bfloat16 *xh, *xl, *wh, *wl, *qh, *ql, *sbf;
    __half *xt;
    float *pm, *cmax, *cs;
    int *cnt; uint2 *ent;
    cudaGetSymbolAddress((void**)&xh, g_xh);  cudaGetSymbolAddress((void**)&xl, g_xl);
    cudaGetSymbolAddress((void**)&xt, g_xt);
    cudaGetSymbolAddress((void**)&wh, g_wh);  cudaGetSymbolAddress((void**)&wl, g_wl);
    cudaGetSymbolAddress((void**)&qh, g_qh);  cudaGetSymbolAddress((void**)&ql, g_ql);
    cudaGetSymbolAddress((void**)&sbf, g_s);
    cudaGetSymbolAddress((void**)&pm, g_pm);
    cudaGetSymbolAddress((void**)&cmax, g_cmax);
    cudaGetSymbolAddress((void**)&cs, g_cs);
    cudaGetSymbolAddress((void**)&cnt, g_cnt);
    cudaGetSymbolAddress((void**)&ent, g_ent);

    int dev = 0;  cudaGetDevice(&dev);
    int nsm = 148;
    cudaDeviceGetAttribute(&nsm, cudaDevAttrMultiProcessorCount, dev);

    const int smemG = STAGES * STAGE_BYTES + STAT_BYTES;
    cudaFuncSetAttribute((const void*)gemm_mma<1, false, 96>, cudaFuncAttributeMaxDynamicSharedMemorySize, smemG);
    cudaFuncSetAttribute((const void*)gemm_mma<2, true, 32>,  cudaFuncAttributeMaxDynamicSharedMemorySize, smemG);

    // prep: X -> xh/xl/xt, W -> wh/wl
    prep<<<dim3(64, 64, 9), 256>>>(X, W, xh, xl, xt, wh, wl);

    const long long sXE = (long long)NN * EE;
    const long long sNN = (long long)NN * NN;

    // GEMM1: Q = X W^T. 3-phase bf16 -> hi/lo bf16 (qh, ql).
    gemm_mma<1, false, 96><<<nsm, 256, smemG>>>(xh, xl, wh, wl, 0, 0, 0,
                                                qh, ql, 16, 64, 1024, nullptr);

    // GEMM2: approx S[b] = Qh[b] Xh[b]^T. 1-phase bf16 -> bf16 S + fused col-max.
    gemm_mma<2, true, 32><<<nsm, 256, smemG>>>(qh, qh, xh, xh, sXE, sXE, sNN,
                                               sbf, nullptr, 16, 8, 1024, pm);

    // approx cmax + zero col-sums; fused extract + exact recompute + col-sum; sparse output.
    col_finish<<<(BATCH * NN) / 256, 256>>>(pm, cmax, cs);
    {
        const int smemE = 8192 * 3 + 128;
        extract_recompute<<<BATCH * NN, 256, smemE>>>(sbf, cmax, qh, ql, X, cnt, ent, cs);
    }
    {
        const int smemS = 256 * 17 * 4 + 256;
        spmm_out<<<dim3(128, BATCH), 256, smemS>>>(xt, cnt, ent, cmax, cs, out);
    }
}